// round 13
// baseline (speedup 1.0000x reference)
#include <cuda_runtime.h>
#include <cuda_fp16.h>
#include <cstdint>

#define NB 64
#define HH 16
#define LL 4096
#define BH 32
#define EPSV 1e-6f
#define BLKU 4160   // per-block u32 in g_dS: 64x64 S^T half2 + 64 Z half2

__device__ uint32_t g_dS[(size_t)BH * NB * BLKU];  // 34 MB fp16 scratch
__device__ uint32_t g_WT[HH * 2048];               // W^T fp16 [h][f][d/2]

__device__ __forceinline__ uint32_t pk(float a, float b) {
    __half2 h = __floats2half2_rn(a, b);
    return *(uint32_t*)&h;
}

__device__ __forceinline__ void mma16(float* c, const uint32_t* a, const uint32_t* b) {
    asm volatile(
        "mma.sync.aligned.m16n8k16.row.col.f32.f16.f16.f32 "
        "{%0,%1,%2,%3},{%4,%5,%6,%7},{%8,%9},{%0,%1,%2,%3};"
        : "+f"(c[0]), "+f"(c[1]), "+f"(c[2]), "+f"(c[3])
        : "r"(a[0]), "r"(a[1]), "r"(a[2]), "r"(a[3]), "r"(b[0]), "r"(b[1]));
}

// x4 non-trans: tiles (r0,k0),(r0+8,k0),(r0,k0+8),(r0+8,k0+8); S = half2 array, ld2 in half2
__device__ __forceinline__ void ldsm4(const uint32_t* S, int ld2, int r0, int k0, uint32_t* d) {
    int lane = threadIdx.x & 31, q = lane >> 3, r = lane & 7;
    const uint32_t* p = S + (r0 + r + 8 * (q & 1)) * ld2 + (k0 >> 1) + 4 * (q >> 1);
    unsigned a = (unsigned)__cvta_generic_to_shared(p);
    asm volatile("ldmatrix.sync.aligned.m8n8.x4.shared.b16 {%0,%1,%2,%3},[%4];"
                 : "=r"(d[0]), "=r"(d[1]), "=r"(d[2]), "=r"(d[3]) : "r"(a));
}
// x4 trans from natural [k][n]: tiles (k0,n0),(k0,n0+8),(k0+8,n0),(k0+8,n0+8)
__device__ __forceinline__ void ldsm4t(const uint32_t* S, int ld2, int k0, int n0, uint32_t* d) {
    int lane = threadIdx.x & 31, q = lane >> 3, r = lane & 7;
    const uint32_t* p = S + (k0 + r + 8 * (q >> 1)) * ld2 + (n0 >> 1) + 4 * (q & 1);
    unsigned a = (unsigned)__cvta_generic_to_shared(p);
    asm volatile("ldmatrix.sync.aligned.m8n8.x4.trans.shared.b16 {%0,%1,%2,%3},[%4];"
                 : "=r"(d[0]), "=r"(d[1]), "=r"(d[2]), "=r"(d[3]) : "r"(a));
}

__device__ __forceinline__ float rmax4(float x) {
    x = fmaxf(x, __shfl_xor_sync(0xffffffffu, x, 1));
    x = fmaxf(x, __shfl_xor_sync(0xffffffffu, x, 2));
    return x;
}
__device__ __forceinline__ float rsum4(float x) {
    x += __shfl_xor_sync(0xffffffffu, x, 1);
    x += __shfl_xor_sync(0xffffffffu, x, 2);
    return x;
}

__device__ __forceinline__ void cp16(void* dst_smem, const void* src_g) {
    unsigned d = (unsigned)__cvta_generic_to_shared(dst_smem);
    asm volatile("cp.async.cg.shared.global [%0], [%1], 16;" :: "r"(d), "l"(src_g));
}
#define CP_COMMIT() asm volatile("cp.async.commit_group;")
#define CP_WAIT0()  asm volatile("cp.async.wait_group 0;")
#define CP_WAIT1()  asm volatile("cp.async.wait_group 1;")

// ======================= Prep: W^T -> fp16 global ================================
__global__ void prep_kernel(const float* __restrict__ W) {
    int h = blockIdx.x, t = threadIdx.x;
    const float* Wh = W + h * 4096;
#pragma unroll
    for (int i = 0; i < 8; i++) {
        int idx = t + 256 * i;              // 0..2047
        int f = idx >> 5, j = idx & 31;     // WT[f][d-pair j]
        g_WT[h * 2048 + f * 32 + j] = pk(Wh[(2 * j) * 64 + f], Wh[(2 * j + 1) * 64 + f]);
    }
}

// ======================= Phase 1: fp16 S^T block deltas + Z ======================
__global__ void __launch_bounds__(256, 3)
phase1_kernel(const float* __restrict__ K, const float* __restrict__ V, int bb) {
    extern __shared__ uint32_t smu[];
    uint32_t* sK   = smu;          // [64][36] k
    uint32_t* sV   = smu + 2304;   // [64][36] v
    uint32_t* sWT  = smu + 4608;   // [64][36] W^T
    uint32_t* sPhi = smu + 6912;   // [64][68] phi
    float*    pex  = (float*)(smu + 11264);  // 512: pmax|pmin|psp|psn  -> 47104 B

    int t = threadIdx.x, w = t >> 5, lane = t & 31, g = lane >> 2, tg = lane & 3;
    int bid = bb * 64 + blockIdx.x, bh = bid >> 6, n = bid & 63, h = bh & (HH - 1);
    size_t xb = ((size_t)bh * LL + (size_t)n * 64) * 64;
    size_t sb = (size_t)bid * BLKU;

#pragma unroll
    for (int i = 0; i < 2; i++) {
        int idx = t + 256 * i;              // 0..511
        int f = idx >> 3, j = idx & 7;
        cp16(sWT + f * 36 + j * 4, g_WT + h * 2048 + f * 32 + j * 4);
    }
    CP_COMMIT();
#pragma unroll
    for (int i = 0; i < 4; i++) {
        int idx = t + 256 * i;              // 0..1023
        int s = idx >> 4, j = idx & 15;
        float4 kx = *(const float4*)&K[xb + s * 64 + 4 * j];
        float4 vx = *(const float4*)&V[xb + s * 64 + 4 * j];
        sK[s * 36 + 2 * j]     = pk(kx.x, kx.y);
        sK[s * 36 + 2 * j + 1] = pk(kx.z, kx.w);
        sV[s * 36 + 2 * j]     = pk(vx.x, vx.y);
        sV[s * 36 + 2 * j + 1] = pk(vx.z, vx.w);
    }
    CP_WAIT0();
    __syncthreads();  // B0

    // u = k @ W spread over ALL 8 warps: warp = (m-tile mt, n-half nh)
    float* pmax = pex, *pmin = pex + 128, *psp = pex + 256, *psn = pex + 384;
    int mt = w >> 1, nh = w & 1, m0 = 16 * mt, r0 = m0 + g, r1 = r0 + 8;
    {
        float u[4][4] = {};
#pragma unroll
        for (int k0 = 0; k0 < 64; k0 += 16) {
            uint32_t a[4]; ldsm4(sK, 36, m0, k0, a);
#pragma unroll
            for (int p = 0; p < 2; p++) {
                uint32_t b[4]; ldsm4(sWT, 36, 16 * (2 * nh + p), k0, b);
                uint32_t b0[2] = {b[0], b[2]}, b1[2] = {b[1], b[3]};
                mma16(u[2 * p], a, b0);
                mma16(u[2 * p + 1], a, b1);
            }
        }
        float hi0 = -3e38f, hi1 = -3e38f, lo0 = 3e38f, lo1 = 3e38f;
#pragma unroll
        for (int nt = 0; nt < 4; nt++) {
            hi0 = fmaxf(hi0, fmaxf(u[nt][0], u[nt][1]));
            lo0 = fminf(lo0, fminf(u[nt][0], u[nt][1]));
            hi1 = fmaxf(hi1, fmaxf(u[nt][2], u[nt][3]));
            lo1 = fminf(lo1, fminf(u[nt][2], u[nt][3]));
        }
        hi0 = rmax4(hi0); hi1 = rmax4(hi1);
        lo0 = -rmax4(-lo0); lo1 = -rmax4(-lo1);
        if (tg == 0) {
            pmax[r0 * 2 + nh] = hi0; pmax[r1 * 2 + nh] = hi1;
            pmin[r0 * 2 + nh] = lo0; pmin[r1 * 2 + nh] = lo1;
        }
        __syncthreads();  // B0a: partial max/min ready
        float HI0 = fmaxf(pmax[r0 * 2], pmax[r0 * 2 + 1]);
        float HI1 = fmaxf(pmax[r1 * 2], pmax[r1 * 2 + 1]);
        float LO0 = fminf(pmin[r0 * 2], pmin[r0 * 2 + 1]);
        float LO1 = fminf(pmin[r1 * 2], pmin[r1 * 2 + 1]);
        float sp0 = 0.f, sp1 = 0.f, sn0 = 0.f, sn1 = 0.f;
#pragma unroll
        for (int nt = 0; nt < 4; nt++) {
            sp0 += __expf(u[nt][0] - HI0) + __expf(u[nt][1] - HI0);
            sn0 += __expf(LO0 - u[nt][0]) + __expf(LO0 - u[nt][1]);
            sp1 += __expf(u[nt][2] - HI1) + __expf(u[nt][3] - HI1);
            sn1 += __expf(LO1 - u[nt][2]) + __expf(LO1 - u[nt][3]);
        }
        sp0 = rsum4(sp0); sp1 = rsum4(sp1); sn0 = rsum4(sn0); sn1 = rsum4(sn1);
        if (tg == 0) {
            psp[r0 * 2 + nh] = sp0; psp[r1 * 2 + nh] = sp1;
            psn[r0 * 2 + nh] = sn0; psn[r1 * 2 + nh] = sn1;
        }
        __syncthreads();  // B0b: partial sums ready
        float rp0 = 1.f / (psp[r0 * 2] + psp[r0 * 2 + 1]);
        float rp1 = 1.f / (psp[r1 * 2] + psp[r1 * 2 + 1]);
        float rn0 = 1.f / (psn[r0 * 2] + psn[r0 * 2 + 1]);
        float rn1 = 1.f / (psn[r1 * 2] + psn[r1 * 2 + 1]);
#pragma unroll
        for (int nt = 0; nt < 4; nt++) {
            int j = 16 * nh + 4 * nt + tg;
            sPhi[r0 * 68 + j]      = pk(__expf(u[nt][0] - HI0) * rp0, __expf(u[nt][1] - HI0) * rp0);
            sPhi[r0 * 68 + 32 + j] = pk(__expf(LO0 - u[nt][0]) * rn0, __expf(LO0 - u[nt][1]) * rn0);
            sPhi[r1 * 68 + j]      = pk(__expf(u[nt][2] - HI1) * rp1, __expf(u[nt][3] - HI1) * rp1);
            sPhi[r1 * 68 + 32 + j] = pk(__expf(LO1 - u[nt][2]) * rn1, __expf(LO1 - u[nt][3]) * rn1);
        }
    }
    __syncthreads();  // B1: phi ready

    // dS^T[d][f] = sum_s v[s][d] * phi[s][f]; A = v^T (trans), B = phi (trans)
    int n0 = 64 * nh;
    float acc[8][4] = {};
#pragma unroll
    for (int k0 = 0; k0 < 64; k0 += 16) {
        uint32_t a[4]; ldsm4t(sV, 36, k0, m0, a);
#pragma unroll
        for (int p = 0; p < 4; p++) {
            uint32_t b[4]; ldsm4t(sPhi, 68, k0, n0 + 16 * p, b);
            uint32_t b0[2] = {b[0], b[2]}, b1[2] = {b[1], b[3]};
            mma16(acc[2 * p], a, b0);
            mma16(acc[2 * p + 1], a, b1);
        }
    }
#pragma unroll
    for (int nt = 0; nt < 8; nt++) {
        int jc = (n0 >> 1) + 4 * nt + tg;   // u32 column
        g_dS[sb + (size_t)(m0 + g) * 64 + jc]     = pk(acc[nt][0], acc[nt][1]);
        g_dS[sb + (size_t)(m0 + g + 8) * 64 + jc] = pk(acc[nt][2], acc[nt][3]);
    }
    if (t < 64) {  // Z: column sums of phi (pair 2t, 2t+1)
        float zx = 0.f, zy = 0.f;
#pragma unroll 8
        for (int s = 0; s < 64; s++) {
            float2 f2 = __half22float2(*(__half2*)&sPhi[s * 68 + t]);
            zx += f2.x; zy += f2.y;
        }
        g_dS[sb + 4096 + t] = pk(zx, zy);
    }
}

// ======================= Exclusive prefix scan (fp16 in/out, fp32 carry) =========
__global__ void scanS_kernel(int bb) {
    int bh = bb + blockIdx.y;
    int e = blockIdx.x * 256 + threadIdx.x;  // uint4 chain 0..1039
    if (e >= 1040) return;
    uint4* p = (uint4*)g_dS;
    size_t base = (size_t)bh * NB * 1040 + e;
    float r[8] = {};
#pragma unroll 4
    for (int n = 0; n < NB; n++) {
        uint4 x = p[base + (size_t)n * 1040];
        uint4 o;
        o.x = pk(r[0], r[1]); o.y = pk(r[2], r[3]);
        o.z = pk(r[4], r[5]); o.w = pk(r[6], r[7]);
        p[base + (size_t)n * 1040] = o;
        float2 f;
        f = __half22float2(*(__half2*)&x.x); r[0] += f.x; r[1] += f.y;
        f = __half22float2(*(__half2*)&x.y); r[2] += f.x; r[3] += f.y;
        f = __half22float2(*(__half2*)&x.z); r[4] += f.x; r[5] += f.y;
        f = __half22float2(*(__half2*)&x.w); r[6] += f.x; r[7] += f.y;
    }
}

// ======================= Phase 2: outputs ========================================
__global__ void __launch_bounds__(256, 3)
phase2_kernel(const float* __restrict__ Q, const float* __restrict__ K,
              const float* __restrict__ V, const float* __restrict__ alpha,
              float* __restrict__ out, int bb) {
    extern __shared__ uint32_t smu[];
    uint32_t* sQ   = smu;           // [64][36] q
    uint32_t* sK   = smu + 2304;    // [64][36] k
    uint32_t* sWV  = smu + 4608;    // [64][36] W^T -> v
    uint32_t* sA   = smu + 6912;    // [64][36] a
    uint32_t* sPhi = smu + 9216;    // [64][68] phi
    uint32_t* sS   = smu + 13568;   // [64][68] S^T (cp.async fp16)
    float*    sZf  = (float*)(smu + 17920);  // 128
    float*    sLd  = (float*)(smu + 18048);  // 64
    float*    sAs  = (float*)(smu + 18112);  // 64  -> 18176 u32 = 72704 B

    int t = threadIdx.x, w = t >> 5, lane = t & 31, g = lane >> 2, tg = lane & 3;
    int bid = bb * 64 + blockIdx.x, bh = bid >> 6, n = bid & 63, h = bh & (HH - 1);
    size_t xb = ((size_t)bh * LL + (size_t)n * 64) * 64;
    const uint32_t* SgU = g_dS + (size_t)bid * BLKU;

    // group 0: W^T
#pragma unroll
    for (int i = 0; i < 2; i++) {
        int idx = t + 256 * i;
        int f = idx >> 3, j = idx & 7;
        cp16(sWV + f * 36 + j * 4, g_WT + h * 2048 + f * 32 + j * 4);
    }
    CP_COMMIT();
    // group 1: S^T prefix (fp16, no conversion) — arrives during phase A/B
#pragma unroll
    for (int i = 0; i < 4; i++) {
        int idx = t + 256 * i;              // 0..1023
        int d = idx >> 4, j = idx & 15;
        cp16(sS + d * 68 + j * 4, SgU + d * 64 + j * 4);
    }
    CP_COMMIT();
    if (t < 64) {
        float2 f2 = __half22float2(*(__half2*)&SgU[4096 + t]);
        sZf[2 * t] = f2.x; sZf[2 * t + 1] = f2.y;
    }
#pragma unroll
    for (int i = 0; i < 4; i++) {
        int idx = t + 256 * i;              // 0..1023
        int s = idx >> 4, j = idx & 15;
        float4 qx = *(const float4*)&Q[xb + s * 64 + 4 * j];
        float4 kx = *(const float4*)&K[xb + s * 64 + 4 * j];
        sQ[s * 36 + 2 * j]     = pk(qx.x, qx.y);
        sQ[s * 36 + 2 * j + 1] = pk(qx.z, qx.w);
        sK[s * 36 + 2 * j]     = pk(kx.x, kx.y);
        sK[s * 36 + 2 * j + 1] = pk(kx.z, kx.w);
    }
    CP_WAIT1();       // W^T done (S may still be in flight)
    __syncthreads();  // B0

    if (w < 4) {
        // u = q @ W, hedgehog phi + lin_den
        int m0 = 16 * w, r0 = m0 + g, r1 = r0 + 8;
        float u[8][4] = {};
#pragma unroll
        for (int k0 = 0; k0 < 64; k0 += 16) {
            uint32_t a[4]; ldsm4(sQ, 36, m0, k0, a);
#pragma unroll
            for (int p = 0; p < 4; p++) {
                uint32_t b[4]; ldsm4(sWV, 36, 16 * p, k0, b);
                uint32_t b0[2] = {b[0], b[2]}, b1[2] = {b[1], b[3]};
                mma16(u[2 * p], a, b0);
                mma16(u[2 * p + 1], a, b1);
            }
        }
        float hi0 = -3e38f, hi1 = -3e38f, lo0 = 3e38f, lo1 = 3e38f;
#pragma unroll
        for (int nt = 0; nt < 8; nt++) {
            hi0 = fmaxf(hi0, fmaxf(u[nt][0], u[nt][1]));
            lo0 = fminf(lo0, fminf(u[nt][0], u[nt][1]));
            hi1 = fmaxf(hi1, fmaxf(u[nt][2], u[nt][3]));
            lo1 = fminf(lo1, fminf(u[nt][2], u[nt][3]));
        }
        hi0 = rmax4(hi0); hi1 = rmax4(hi1);
        lo0 = -rmax4(-lo0); lo1 = -rmax4(-lo1);
        float sp0 = 0.f, sp1 = 0.f, sn0 = 0.f, sn1 = 0.f;
#pragma unroll
        for (int nt = 0; nt < 8; nt++) {
            sp0 += __expf(u[nt][0] - hi0) + __expf(u[nt][1] - hi0);
            sn0 += __expf(lo0 - u[nt][0]) + __expf(lo0 - u[nt][1]);
            sp1 += __expf(u[nt][2] - hi1) + __expf(u[nt][3] - hi1);
            sn1 += __expf(lo1 - u[nt][2]) + __expf(lo1 - u[nt][3]);
        }
        sp0 = rsum4(sp0); sp1 = rsum4(sp1); sn0 = rsum4(sn0); sn1 = rsum4(sn1);
        float rp0 = 1.f / sp0, rp1 = 1.f / sp1, rn0 = 1.f / sn0, rn1 = 1.f / sn1;
        float ld0 = 0.f, ld1 = 0.f;
#pragma unroll
        for (int nt = 0; nt < 8; nt++) {
            int c = 8 * nt + 2 * tg, j = 4 * nt + tg;
            float p00 = __expf(u[nt][0] - hi0) * rp0, p01 = __expf(u[nt][1] - hi0) * rp0;
            float q00 = __expf(lo0 - u[nt][0]) * rn0, q01 = __expf(lo0 - u[nt][1]) * rn0;
            float p10 = __expf(u[nt][2] - hi1) * rp1, p11 = __expf(u[nt][3] - hi1) * rp1;
            float q10 = __expf(lo1 - u[nt][2]) * rn1, q11 = __expf(lo1 - u[nt][3]) * rn1;
            sPhi[r0 * 68 + j]      = pk(p00, p01);
            sPhi[r0 * 68 + 32 + j] = pk(q00, q01);
            sPhi[r1 * 68 + j]      = pk(p10, p11);
            sPhi[r1 * 68 + 32 + j] = pk(q10, q11);
            ld0 += p00 * sZf[c] + p01 * sZf[c + 1] + q00 * sZf[64 + c] + q01 * sZf[65 + c];
            ld1 += p10 * sZf[c] + p11 * sZf[c + 1] + q10 * sZf[64 + c] + q11 * sZf[65 + c];
        }
        ld0 = rsum4(ld0); ld1 = rsum4(ld1);
        if (tg == 0) { sLd[r0] = ld0; sLd[r1] = ld1; }
    } else {
        // scores = q @ k^T, softmax -> a
        int m0 = 16 * (w - 4), r0 = m0 + g, r1 = r0 + 8;
        float sc[8][4] = {};
#pragma unroll
        for (int k0 = 0; k0 < 64; k0 += 16) {
            uint32_t a[4]; ldsm4(sQ, 36, m0, k0, a);
#pragma unroll
            for (int p = 0; p < 4; p++) {
                uint32_t b[4]; ldsm4(sK, 36, 16 * p, k0, b);
                uint32_t b0[2] = {b[0], b[2]}, b1[2] = {b[1], b[3]};
                mma16(sc[2 * p], a, b0);
                mma16(sc[2 * p + 1], a, b1);
            }
        }
        float mx0 = -3e38f, mx1 = -3e38f;
#pragma unroll
        for (int nt = 0; nt < 8; nt++) {
            sc[nt][0] *= 0.125f; sc[nt][1] *= 0.125f;
            sc[nt][2] *= 0.125f; sc[nt][3] *= 0.125f;
            mx0 = fmaxf(mx0, fmaxf(sc[nt][0], sc[nt][1]));
            mx1 = fmaxf(mx1, fmaxf(sc[nt][2], sc[nt][3]));
        }
        mx0 = rmax4(mx0); mx1 = rmax4(mx1);
        float as0 = 0.f, as1 = 0.f;
#pragma unroll
        for (int nt = 0; nt < 8; nt++) {
            sc[nt][0] = __expf(sc[nt][0] - mx0); sc[nt][1] = __expf(sc[nt][1] - mx0);
            sc[nt][2] = __expf(sc[nt][2] - mx1); sc[nt][3] = __expf(sc[nt][3] - mx1);
            as0 += sc[nt][0] + sc[nt][1];
            as1 += sc[nt][2] + sc[nt][3];
        }
        as0 = rsum4(as0); as1 = rsum4(as1);
        if (tg == 0) { sAs[r0] = as0; sAs[r1] = as1; }
#pragma unroll
        for (int nt = 0; nt < 8; nt++) {
            int j = 4 * nt + tg;
            sA[r0 * 36 + j] = pk(sc[nt][0], sc[nt][1]);
            sA[r1 * 36 + j] = pk(sc[nt][2], sc[nt][3]);
        }
    }
    __syncthreads();  // B1: phi, a, sLd, sAs ready; q/k/W^T dead

    // v into the dead W^T buffer
#pragma unroll
    for (int i = 0; i < 4; i++) {
        int idx = t + 256 * i;
        int s = idx >> 4, j = idx & 15;
        float4 vx = *(const float4*)&V[xb + s * 64 + 4 * j];
        sWV[s * 36 + 2 * j]     = pk(vx.x, vx.y);
        sWV[s * 36 + 2 * j + 1] = pk(vx.z, vx.w);
    }
    CP_WAIT0();       // S^T arrived long ago
    __syncthreads();  // B2: v + S visible

    int mt = w >> 1, nh = w & 1, m0 = 16 * mt, n0 = 32 * nh, r0 = m0 + g, r1 = r0 + 8;

    // lin = phi @ S (B = S^T rows, non-trans), sm = a @ v (B = v natural, trans)
    float li[4][4] = {}, sm_[4][4] = {};
#pragma unroll
    for (int k0 = 0; k0 < 128; k0 += 16) {
        uint32_t a[4]; ldsm4(sPhi, 68, m0, k0, a);
#pragma unroll
        for (int p = 0; p < 2; p++) {
            uint32_t b[4]; ldsm4(sS, 68, n0 + 16 * p, k0, b);
            uint32_t b0[2] = {b[0], b[2]}, b1[2] = {b[1], b[3]};
            mma16(li[2 * p], a, b0);
            mma16(li[2 * p + 1], a, b1);
        }
    }
#pragma unroll
    for (int k0 = 0; k0 < 64; k0 += 16) {
        uint32_t a[4]; ldsm4(sA, 36, m0, k0, a);
#pragma unroll
        for (int p = 0; p < 2; p++) {
            uint32_t b[4]; ldsm4t(sWV, 36, k0, n0 + 16 * p, b);
            uint32_t b0[2] = {b[0], b[2]}, b1[2] = {b[1], b[3]};
            mma16(sm_[2 * p], a, b0);
            mma16(sm_[2 * p + 1], a, b1);
        }
    }

    float wgt = 1.f / (1.f + __expf(-alpha[h]));
    float den0 = fmaxf(wgt * fmaxf(sAs[r0], EPSV) + fmaxf(sLd[r0], EPSV), EPSV);
    float den1 = fmaxf(wgt * fmaxf(sAs[r1], EPSV) + fmaxf(sLd[r1], EPSV), EPSV);
    float id0 = 1.f / den0, id1 = 1.f / den1;
#pragma unroll
    for (int nt = 0; nt < 4; nt++) {
        int c = n0 + 8 * nt + 2 * tg;
        float2 o0, o1;
        o0.x = (wgt * sm_[nt][0] + li[nt][0]) * id0;
        o0.y = (wgt * sm_[nt][1] + li[nt][1]) * id0;
        o1.x = (wgt * sm_[nt][2] + li[nt][2]) * id1;
        o1.y = (wgt * sm_[nt][3] + li[nt][3]) * id1;
        *(float2*)&out[xb + (size_t)r0 * 64 + c] = o0;
        *(float2*)&out[xb + (size_t)r1 * 64 + c] = o1;
    }
}

// ---- host-side pipeline resources (host objects only; created at load time) ----
namespace {
struct PipeRes {
    cudaStream_t sa, sb;
    cudaEvent_t evF, ev1a, evDA, evDB;
    PipeRes() {
        cudaStreamCreateWithFlags(&sa, cudaStreamNonBlocking);
        cudaStreamCreateWithFlags(&sb, cudaStreamNonBlocking);
        cudaEventCreateWithFlags(&evF, cudaEventDisableTiming);
        cudaEventCreateWithFlags(&ev1a, cudaEventDisableTiming);
        cudaEventCreateWithFlags(&evDA, cudaEventDisableTiming);
        cudaEventCreateWithFlags(&evDB, cudaEventDisableTiming);
    }
};
PipeRes g_pr;
}

extern "C" void kernel_launch(void* const* d_in, const int* in_sizes, int n_in,
                              void* d_out, int out_size) {
    const float* Q = (const float*)d_in[0];
    const float* K = (const float*)d_in[1];
    const float* V = (const float*)d_in[2];
    const float* W = (const float*)d_in[3];
    const float* A = (const float*)d_in[4];
    float* out = (float*)d_out;

    cudaFuncSetAttribute(phase1_kernel, cudaFuncAttributeMaxDynamicSharedMemorySize, 47104);
    cudaFuncSetAttribute(phase2_kernel, cudaFuncAttributeMaxDynamicSharedMemorySize, 72704);

    // origin stream: prep, then fork
    prep_kernel<<<HH, 256>>>(W);
    cudaEventRecord(g_pr.evF, 0);

    // stream A: group bh 0..15
    cudaStreamWaitEvent(g_pr.sa, g_pr.evF, 0);
    phase1_kernel<<<16 * NB, 256, 47104, g_pr.sa>>>(K, V, 0);
    cudaEventRecord(g_pr.ev1a, g_pr.sa);
    scanS_kernel<<<dim3(5, 16), 256, 0, g_pr.sa>>>(0);
    phase2_kernel<<<16 * NB, 256, 72704, g_pr.sa>>>(Q, K, V, A, out, 0);
    cudaEventRecord(g_pr.evDA, g_pr.sa);

    // stream B: group bh 16..31, staggered after A's phase1
    cudaStreamWaitEvent(g_pr.sb, g_pr.ev1a, 0);
    phase1_kernel<<<16 * NB, 256, 47104, g_pr.sb>>>(K, V, 16);
    scanS_kernel<<<dim3(5, 16), 256, 0, g_pr.sb>>>(16);
    phase2_kernel<<<16 * NB, 256, 72704, g_pr.sb>>>(Q, K, V, A, out, 16);
    cudaEventRecord(g_pr.evDB, g_pr.sb);

    // join back into origin stream
    cudaStreamWaitEvent(0, g_pr.evDA, 0);
    cudaStreamWaitEvent(0, g_pr.evDB, 0);
}

// round 14
// speedup vs baseline: 1.1347x; 1.1347x over previous
#include <cuda_runtime.h>
#include <cuda_fp16.h>
#include <cstdint>

#define NB 64
#define HH 16
#define LL 4096
#define BH 32
#define EPSV 1e-6f
#define BLKU 4160   // per-block u32 in g_dS: 64x64 S^T half2 + 64 Z half2

__device__ uint32_t g_dS[(size_t)BH * NB * BLKU];  // 34 MB fp16 scratch
__device__ uint32_t g_WT[HH * 2048];               // W^T fp16 [h][f][d/2]

__device__ __forceinline__ uint32_t pk(float a, float b) {
    __half2 h = __floats2half2_rn(a, b);
    return *(uint32_t*)&h;
}

__device__ __forceinline__ void mma16(float* c, const uint32_t* a, const uint32_t* b) {
    asm volatile(
        "mma.sync.aligned.m16n8k16.row.col.f32.f16.f16.f32 "
        "{%0,%1,%2,%3},{%4,%5,%6,%7},{%8,%9},{%0,%1,%2,%3};"
        : "+f"(c[0]), "+f"(c[1]), "+f"(c[2]), "+f"(c[3])
        : "r"(a[0]), "r"(a[1]), "r"(a[2]), "r"(a[3]), "r"(b[0]), "r"(b[1]));
}

// x4 non-trans: tiles (r0,k0),(r0+8,k0),(r0,k0+8),(r0+8,k0+8); S = half2 array, ld2 in half2
__device__ __forceinline__ void ldsm4(const uint32_t* S, int ld2, int r0, int k0, uint32_t* d) {
    int lane = threadIdx.x & 31, q = lane >> 3, r = lane & 7;
    const uint32_t* p = S + (r0 + r + 8 * (q & 1)) * ld2 + (k0 >> 1) + 4 * (q >> 1);
    unsigned a = (unsigned)__cvta_generic_to_shared(p);
    asm volatile("ldmatrix.sync.aligned.m8n8.x4.shared.b16 {%0,%1,%2,%3},[%4];"
                 : "=r"(d[0]), "=r"(d[1]), "=r"(d[2]), "=r"(d[3]) : "r"(a));
}
// x4 trans from natural [k][n]: tiles (k0,n0),(k0,n0+8),(k0+8,n0),(k0+8,n0+8)
__device__ __forceinline__ void ldsm4t(const uint32_t* S, int ld2, int k0, int n0, uint32_t* d) {
    int lane = threadIdx.x & 31, q = lane >> 3, r = lane & 7;
    const uint32_t* p = S + (k0 + r + 8 * (q >> 1)) * ld2 + (n0 >> 1) + 4 * (q & 1);
    unsigned a = (unsigned)__cvta_generic_to_shared(p);
    asm volatile("ldmatrix.sync.aligned.m8n8.x4.trans.shared.b16 {%0,%1,%2,%3},[%4];"
                 : "=r"(d[0]), "=r"(d[1]), "=r"(d[2]), "=r"(d[3]) : "r"(a));
}

__device__ __forceinline__ float rmax4(float x) {
    x = fmaxf(x, __shfl_xor_sync(0xffffffffu, x, 1));
    x = fmaxf(x, __shfl_xor_sync(0xffffffffu, x, 2));
    return x;
}
__device__ __forceinline__ float rsum4(float x) {
    x += __shfl_xor_sync(0xffffffffu, x, 1);
    x += __shfl_xor_sync(0xffffffffu, x, 2);
    return x;
}

__device__ __forceinline__ void cp16(void* dst_smem, const void* src_g) {
    unsigned d = (unsigned)__cvta_generic_to_shared(dst_smem);
    asm volatile("cp.async.cg.shared.global [%0], [%1], 16;" :: "r"(d), "l"(src_g));
}
#define CP_COMMIT() asm volatile("cp.async.commit_group;")
#define CP_WAIT0()  asm volatile("cp.async.wait_group 0;")

// ======================= Prep: W^T -> fp16 global ================================
__global__ void prep_kernel(const float* __restrict__ W) {
    int h = blockIdx.x, t = threadIdx.x;
    const float* Wh = W + h * 4096;
#pragma unroll
    for (int i = 0; i < 8; i++) {
        int idx = t + 256 * i;              // 0..2047
        int f = idx >> 5, j = idx & 31;     // WT[f][d-pair j]
        g_WT[h * 2048 + f * 32 + j] = pk(Wh[(2 * j) * 64 + f], Wh[(2 * j + 1) * 64 + f]);
    }
}

// ======================= Phase 1: fp16 S^T block deltas + Z ======================
__global__ void __launch_bounds__(256, 3)
phase1_kernel(const float* __restrict__ K, const float* __restrict__ V) {
    extern __shared__ uint32_t smu[];
    uint32_t* sK   = smu;          // [64][36] k
    uint32_t* sV   = smu + 2304;   // [64][36] v
    uint32_t* sWT  = smu + 4608;   // [64][36] W^T
    uint32_t* sPhi = smu + 6912;   // [64][68] phi
    float*    pex  = (float*)(smu + 11264);  // 512: pmax|pmin|psp|psn  -> 47104 B

    int t = threadIdx.x, w = t >> 5, lane = t & 31, g = lane >> 2, tg = lane & 3;
    int bid = blockIdx.x, bh = bid >> 6, n = bid & 63, h = bh & (HH - 1);
    size_t xb = ((size_t)bh * LL + (size_t)n * 64) * 64;
    size_t sb = (size_t)bid * BLKU;

#pragma unroll
    for (int i = 0; i < 2; i++) {
        int idx = t + 256 * i;              // 0..511
        int f = idx >> 3, j = idx & 7;
        cp16(sWT + f * 36 + j * 4, g_WT + h * 2048 + f * 32 + j * 4);
    }
    CP_COMMIT();
#pragma unroll
    for (int i = 0; i < 4; i++) {
        int idx = t + 256 * i;              // 0..1023
        int s = idx >> 4, j = idx & 15;
        float4 kx = *(const float4*)&K[xb + s * 64 + 4 * j];
        float4 vx = *(const float4*)&V[xb + s * 64 + 4 * j];
        sK[s * 36 + 2 * j]     = pk(kx.x, kx.y);
        sK[s * 36 + 2 * j + 1] = pk(kx.z, kx.w);
        sV[s * 36 + 2 * j]     = pk(vx.x, vx.y);
        sV[s * 36 + 2 * j + 1] = pk(vx.z, vx.w);
    }
    CP_WAIT0();
    __syncthreads();  // B0

    // u = k @ W spread over ALL 8 warps: warp = (m-tile mt, n-half nh)
    float* pmax = pex, *pmin = pex + 128, *psp = pex + 256, *psn = pex + 384;
    int mt = w >> 1, nh = w & 1, m0 = 16 * mt, r0 = m0 + g, r1 = r0 + 8;
    {
        float u[4][4] = {};
#pragma unroll
        for (int k0 = 0; k0 < 64; k0 += 16) {
            uint32_t a[4]; ldsm4(sK, 36, m0, k0, a);
#pragma unroll
            for (int p = 0; p < 2; p++) {
                uint32_t b[4]; ldsm4(sWT, 36, 16 * (2 * nh + p), k0, b);
                uint32_t b0[2] = {b[0], b[2]}, b1[2] = {b[1], b[3]};
                mma16(u[2 * p], a, b0);
                mma16(u[2 * p + 1], a, b1);
            }
        }
        float hi0 = -3e38f, hi1 = -3e38f, lo0 = 3e38f, lo1 = 3e38f;
#pragma unroll
        for (int nt = 0; nt < 4; nt++) {
            hi0 = fmaxf(hi0, fmaxf(u[nt][0], u[nt][1]));
            lo0 = fminf(lo0, fminf(u[nt][0], u[nt][1]));
            hi1 = fmaxf(hi1, fmaxf(u[nt][2], u[nt][3]));
            lo1 = fminf(lo1, fminf(u[nt][2], u[nt][3]));
        }
        hi0 = rmax4(hi0); hi1 = rmax4(hi1);
        lo0 = -rmax4(-lo0); lo1 = -rmax4(-lo1);
        if (tg == 0) {
            pmax[r0 * 2 + nh] = hi0; pmax[r1 * 2 + nh] = hi1;
            pmin[r0 * 2 + nh] = lo0; pmin[r1 * 2 + nh] = lo1;
        }
        __syncthreads();  // B0a: partial max/min ready
        float HI0 = fmaxf(pmax[r0 * 2], pmax[r0 * 2 + 1]);
        float HI1 = fmaxf(pmax[r1 * 2], pmax[r1 * 2 + 1]);
        float LO0 = fminf(pmin[r0 * 2], pmin[r0 * 2 + 1]);
        float LO1 = fminf(pmin[r1 * 2], pmin[r1 * 2 + 1]);
        float sp0 = 0.f, sp1 = 0.f, sn0 = 0.f, sn1 = 0.f;
#pragma unroll
        for (int nt = 0; nt < 4; nt++) {
            sp0 += __expf(u[nt][0] - HI0) + __expf(u[nt][1] - HI0);
            sn0 += __expf(LO0 - u[nt][0]) + __expf(LO0 - u[nt][1]);
            sp1 += __expf(u[nt][2] - HI1) + __expf(u[nt][3] - HI1);
            sn1 += __expf(LO1 - u[nt][2]) + __expf(LO1 - u[nt][3]);
        }
        sp0 = rsum4(sp0); sp1 = rsum4(sp1); sn0 = rsum4(sn0); sn1 = rsum4(sn1);
        if (tg == 0) {
            psp[r0 * 2 + nh] = sp0; psp[r1 * 2 + nh] = sp1;
            psn[r0 * 2 + nh] = sn0; psn[r1 * 2 + nh] = sn1;
        }
        __syncthreads();  // B0b: partial sums ready
        float rp0 = 1.f / (psp[r0 * 2] + psp[r0 * 2 + 1]);
        float rp1 = 1.f / (psp[r1 * 2] + psp[r1 * 2 + 1]);
        float rn0 = 1.f / (psn[r0 * 2] + psn[r0 * 2 + 1]);
        float rn1 = 1.f / (psn[r1 * 2] + psn[r1 * 2 + 1]);
#pragma unroll
        for (int nt = 0; nt < 4; nt++) {
            int j = 16 * nh + 4 * nt + tg;
            sPhi[r0 * 68 + j]      = pk(__expf(u[nt][0] - HI0) * rp0, __expf(u[nt][1] - HI0) * rp0);
            sPhi[r0 * 68 + 32 + j] = pk(__expf(LO0 - u[nt][0]) * rn0, __expf(LO0 - u[nt][1]) * rn0);
            sPhi[r1 * 68 + j]      = pk(__expf(u[nt][2] - HI1) * rp1, __expf(u[nt][3] - HI1) * rp1);
            sPhi[r1 * 68 + 32 + j] = pk(__expf(LO1 - u[nt][2]) * rn1, __expf(LO1 - u[nt][3]) * rn1);
        }
    }
    __syncthreads();  // B1: phi ready

    // dS^T[d][f] = sum_s v[s][d] * phi[s][f]; A = v^T (trans), B = phi (trans)
    int n0 = 64 * nh;
    float acc[8][4] = {};
#pragma unroll
    for (int k0 = 0; k0 < 64; k0 += 16) {
        uint32_t a[4]; ldsm4t(sV, 36, k0, m0, a);
#pragma unroll
        for (int p = 0; p < 4; p++) {
            uint32_t b[4]; ldsm4t(sPhi, 68, k0, n0 + 16 * p, b);
            uint32_t b0[2] = {b[0], b[2]}, b1[2] = {b[1], b[3]};
            mma16(acc[2 * p], a, b0);
            mma16(acc[2 * p + 1], a, b1);
        }
    }
#pragma unroll
    for (int nt = 0; nt < 8; nt++) {
        int jc = (n0 >> 1) + 4 * nt + tg;   // u32 column
        g_dS[sb + (size_t)(m0 + g) * 64 + jc]     = pk(acc[nt][0], acc[nt][1]);
        g_dS[sb + (size_t)(m0 + g + 8) * 64 + jc] = pk(acc[nt][2], acc[nt][3]);
    }
    if (t < 64) {  // Z: column sums of phi (pair 2t, 2t+1)
        float zx = 0.f, zy = 0.f;
#pragma unroll 8
        for (int s = 0; s < 64; s++) {
            float2 f2 = __half22float2(*(__half2*)&sPhi[s * 68 + t]);
            zx += f2.x; zy += f2.y;
        }
        g_dS[sb + 4096 + t] = pk(zx, zy);
    }
}

// ======================= Exclusive prefix scan (fp16 in/out, fp32 carry) =========
__global__ void scanS_kernel() {
    int bh = blockIdx.y;
    int e = blockIdx.x * 256 + threadIdx.x;  // uint4 chain 0..1039
    if (e >= 1040) return;
    uint4* p = (uint4*)g_dS;
    size_t base = (size_t)bh * NB * 1040 + e;
    float r[8] = {};
#pragma unroll 4
    for (int n = 0; n < NB; n++) {
        uint4 x = p[base + (size_t)n * 1040];
        uint4 o;
        o.x = pk(r[0], r[1]); o.y = pk(r[2], r[3]);
        o.z = pk(r[4], r[5]); o.w = pk(r[6], r[7]);
        p[base + (size_t)n * 1040] = o;
        float2 f;
        f = __half22float2(*(__half2*)&x.x); r[0] += f.x; r[1] += f.y;
        f = __half22float2(*(__half2*)&x.y); r[2] += f.x; r[3] += f.y;
        f = __half22float2(*(__half2*)&x.z); r[4] += f.x; r[5] += f.y;
        f = __half22float2(*(__half2*)&x.w); r[6] += f.x; r[7] += f.y;
    }
}

// ======================= Phase 2: outputs (4 CTAs/SM) ============================
__global__ void __launch_bounds__(256, 4)
phase2_kernel(const float* __restrict__ Q, const float* __restrict__ K,
              const float* __restrict__ V, const float* __restrict__ alpha,
              float* __restrict__ out) {
    extern __shared__ uint32_t smu[];
    uint32_t* sQ   = smu;           // [64][36] q   } after B1 both host S^T [64][68]
    uint32_t* sK   = smu + 2304;    // [64][36] k   }
    uint32_t* sWV  = smu + 4608;    // [64][36] W^T -> v
    uint32_t* sA   = smu + 6912;    // [64][36] a (stored after B1)
    uint32_t* sPhi = smu + 9216;    // [64][68] phi
    float*    sZf  = (float*)(smu + 13568);  // 128
    float*    sLd  = (float*)(smu + 13696);  // 64
    float*    sAs  = (float*)(smu + 13760);  // 64  -> 13824 u32 = 55296 B
    uint32_t* sS   = smu;           // S^T alias (stride 68, spans 0..4352 < 4608)

    int t = threadIdx.x, w = t >> 5, lane = t & 31, g = lane >> 2, tg = lane & 3;
    int bid = blockIdx.x, bh = bid >> 6, n = bid & 63, h = bh & (HH - 1);
    size_t xb = ((size_t)bh * LL + (size_t)n * 64) * 64;
    const uint32_t* SgU = g_dS + (size_t)bid * BLKU;

    // W^T via cp.async
#pragma unroll
    for (int i = 0; i < 2; i++) {
        int idx = t + 256 * i;
        int f = idx >> 3, j = idx & 7;
        cp16(sWV + f * 36 + j * 4, g_WT + h * 2048 + f * 32 + j * 4);
    }
    CP_COMMIT();
    if (t < 64) {
        float2 f2 = __half22float2(*(__half2*)&SgU[4096 + t]);
        sZf[2 * t] = f2.x; sZf[2 * t + 1] = f2.y;
    }
#pragma unroll
    for (int i = 0; i < 4; i++) {
        int idx = t + 256 * i;              // 0..1023
        int s = idx >> 4, j = idx & 15;
        float4 qx = *(const float4*)&Q[xb + s * 64 + 4 * j];
        float4 kx = *(const float4*)&K[xb + s * 64 + 4 * j];
        sQ[s * 36 + 2 * j]     = pk(qx.x, qx.y);
        sQ[s * 36 + 2 * j + 1] = pk(qx.z, qx.w);
        sK[s * 36 + 2 * j]     = pk(kx.x, kx.y);
        sK[s * 36 + 2 * j + 1] = pk(kx.z, kx.w);
    }
    CP_WAIT0();
    __syncthreads();  // B0

    float aw[8][4];   // score warps' a (held across B1)
    if (w < 4) {
        // u = q @ W, hedgehog phi + lin_den
        int m0 = 16 * w, r0 = m0 + g, r1 = r0 + 8;
        float u[8][4] = {};
#pragma unroll
        for (int k0 = 0; k0 < 64; k0 += 16) {
            uint32_t a[4]; ldsm4(sQ, 36, m0, k0, a);
#pragma unroll
            for (int p = 0; p < 4; p++) {
                uint32_t b[4]; ldsm4(sWV, 36, 16 * p, k0, b);
                uint32_t b0[2] = {b[0], b[2]}, b1[2] = {b[1], b[3]};
                mma16(u[2 * p], a, b0);
                mma16(u[2 * p + 1], a, b1);
            }
        }
        float hi0 = -3e38f, hi1 = -3e38f, lo0 = 3e38f, lo1 = 3e38f;
#pragma unroll
        for (int nt = 0; nt < 8; nt++) {
            hi0 = fmaxf(hi0, fmaxf(u[nt][0], u[nt][1]));
            lo0 = fminf(lo0, fminf(u[nt][0], u[nt][1]));
            hi1 = fmaxf(hi1, fmaxf(u[nt][2], u[nt][3]));
            lo1 = fminf(lo1, fminf(u[nt][2], u[nt][3]));
        }
        hi0 = rmax4(hi0); hi1 = rmax4(hi1);
        lo0 = -rmax4(-lo0); lo1 = -rmax4(-lo1);
        float sp0 = 0.f, sp1 = 0.f, sn0 = 0.f, sn1 = 0.f;
#pragma unroll
        for (int nt = 0; nt < 8; nt++) {
            sp0 += __expf(u[nt][0] - hi0) + __expf(u[nt][1] - hi0);
            sn0 += __expf(lo0 - u[nt][0]) + __expf(lo0 - u[nt][1]);
            sp1 += __expf(u[nt][2] - hi1) + __expf(u[nt][3] - hi1);
            sn1 += __expf(lo1 - u[nt][2]) + __expf(lo1 - u[nt][3]);
        }
        sp0 = rsum4(sp0); sp1 = rsum4(sp1); sn0 = rsum4(sn0); sn1 = rsum4(sn1);
        float rp0 = 1.f / sp0, rp1 = 1.f / sp1, rn0 = 1.f / sn0, rn1 = 1.f / sn1;
        float ld0 = 0.f, ld1 = 0.f;
#pragma unroll
        for (int nt = 0; nt < 8; nt++) {
            int c = 8 * nt + 2 * tg, j = 4 * nt + tg;
            float p00 = __expf(u[nt][0] - hi0) * rp0, p01 = __expf(u[nt][1] - hi0) * rp0;
            float q00 = __expf(lo0 - u[nt][0]) * rn0, q01 = __expf(lo0 - u[nt][1]) * rn0;
            float p10 = __expf(u[nt][2] - hi1) * rp1, p11 = __expf(u[nt][3] - hi1) * rp1;
            float q10 = __expf(lo1 - u[nt][2]) * rn1, q11 = __expf(lo1 - u[nt][3]) * rn1;
            sPhi[r0 * 68 + j]      = pk(p00, p01);
            sPhi[r0 * 68 + 32 + j] = pk(q00, q01);
            sPhi[r1 * 68 + j]      = pk(p10, p11);
            sPhi[r1 * 68 + 32 + j] = pk(q10, q11);
            ld0 += p00 * sZf[c] + p01 * sZf[c + 1] + q00 * sZf[64 + c] + q01 * sZf[65 + c];
            ld1 += p10 * sZf[c] + p11 * sZf[c + 1] + q10 * sZf[64 + c] + q11 * sZf[65 + c];
        }
        ld0 = rsum4(ld0); ld1 = rsum4(ld1);
        if (tg == 0) { sLd[r0] = ld0; sLd[r1] = ld1; }
    } else {
        // scores = q @ k^T, softmax -> aw (regs)
        int m0 = 16 * (w - 4), r0 = m0 + g, r1 = r0 + 8;
        float sc[8][4] = {};
#pragma unroll
        for (int k0 = 0; k0 < 64; k0 += 16) {
            uint32_t a[4]; ldsm4(sQ, 36, m0, k0, a);
#pragma unroll
            for (int p = 0; p < 4; p++) {
                uint32_t b[4]; ldsm4(sK, 36, 16 * p, k0, b);
                uint32_t b0[2] = {b[0], b[2]}, b1[2] = {b[1], b[3]};
                mma16(sc[2 * p], a, b0);
                mma16(sc[2 * p + 1], a, b1);
            }
        }
        float mx0 = -3e38f, mx1 = -3e38f;
#pragma unroll
        for (int nt = 0; nt < 8; nt++) {
            sc[nt][0] *= 0.125f; sc[nt][1] *= 0.125f;
            sc[nt][2] *= 0.125f; sc[nt][3] *= 0.125f;
            mx0 = fmaxf(mx0, fmaxf(sc[nt][0], sc[nt][1]));
            mx1 = fmaxf(mx1, fmaxf(sc[nt][2], sc[nt][3]));
        }
        mx0 = rmax4(mx0); mx1 = rmax4(mx1);
        float as0 = 0.f, as1 = 0.f;
#pragma unroll
        for (int nt = 0; nt < 8; nt++) {
            aw[nt][0] = __expf(sc[nt][0] - mx0); aw[nt][1] = __expf(sc[nt][1] - mx0);
            aw[nt][2] = __expf(sc[nt][2] - mx1); aw[nt][3] = __expf(sc[nt][3] - mx1);
            as0 += aw[nt][0] + aw[nt][1];
            as1 += aw[nt][2] + aw[nt][3];
        }
        as0 = rsum4(as0); as1 = rsum4(as1);
        if (tg == 0) { sAs[r0] = as0; sAs[r1] = as1; }
    }
    __syncthreads();  // B1: phi, sLd, sAs ready; q/k/W^T dead

    // S^T prefetch into dead q+k region (L2-resident; overlaps a/v staging)
#pragma unroll
    for (int i = 0; i < 4; i++) {
        int idx = t + 256 * i;              // 0..1023
        int d = idx >> 4, j = idx & 15;
        cp16(sS + d * 68 + j * 4, SgU + d * 64 + j * 4);
    }
    CP_COMMIT();

    if (w >= 4) {   // store a now that k is dead
        int r0 = 16 * (w - 4) + g, r1 = r0 + 8;
#pragma unroll
        for (int nt = 0; nt < 8; nt++) {
            int j = 4 * nt + tg;
            sA[r0 * 36 + j] = pk(aw[nt][0], aw[nt][1]);
            sA[r1 * 36 + j] = pk(aw[nt][2], aw[nt][3]);
        }
    }
    // v into the dead W^T buffer
#pragma unroll
    for (int i = 0; i < 4; i++) {
        int idx = t + 256 * i;
        int s = idx >> 4, j = idx & 15;
        float4 vx = *(const float4*)&V[xb + s * 64 + 4 * j];
        sWV[s * 36 + 2 * j]     = pk(vx.x, vx.y);
        sWV[s * 36 + 2 * j + 1] = pk(vx.z, vx.w);
    }
    CP_WAIT0();
    __syncthreads();  // B2: S, a, v visible

    int mt = w >> 1, nh = w & 1, m0 = 16 * mt, n0 = 32 * nh, r0 = m0 + g, r1 = r0 + 8;

    // lin = phi @ S (B = S^T rows, non-trans), sm = a @ v (B = v natural, trans)
    float li[4][4] = {}, sm_[4][4] = {};
#pragma unroll
    for (int k0 = 0; k0 < 128; k0 += 16) {
        uint32_t a[4]; ldsm4(sPhi, 68, m0, k0, a);
#pragma unroll
        for (int p = 0; p < 2; p++) {
            uint32_t b[4]; ldsm4(sS, 68, n0 + 16 * p, k0, b);
            uint32_t b0[2] = {b[0], b[2]}, b1[2] = {b[1], b[3]};
            mma16(li[2 * p], a, b0);
            mma16(li[2 * p + 1], a, b1);
        }
    }
#pragma unroll
    for (int k0 = 0; k0 < 64; k0 += 16) {
        uint32_t a[4]; ldsm4(sA, 36, m0, k0, a);
#pragma unroll
        for (int p = 0; p < 2; p++) {
            uint32_t b[4]; ldsm4t(sWV, 36, k0, n0 + 16 * p, b);
            uint32_t b0[2] = {b[0], b[2]}, b1[2] = {b[1], b[3]};
            mma16(sm_[2 * p], a, b0);
            mma16(sm_[2 * p + 1], a, b1);
        }
    }

    float wgt = 1.f / (1.f + __expf(-alpha[h]));
    float den0 = fmaxf(wgt * fmaxf(sAs[r0], EPSV) + fmaxf(sLd[r0], EPSV), EPSV);
    float den1 = fmaxf(wgt * fmaxf(sAs[r1], EPSV) + fmaxf(sLd[r1], EPSV), EPSV);
    float id0 = 1.f / den0, id1 = 1.f / den1;
#pragma unroll
    for (int nt = 0; nt < 4; nt++) {
        int c = n0 + 8 * nt + 2 * tg;
        float2 o0, o1;
        o0.x = (wgt * sm_[nt][0] + li[nt][0]) * id0;
        o0.y = (wgt * sm_[nt][1] + li[nt][1]) * id0;
        o1.x = (wgt * sm_[nt][2] + li[nt][2]) * id1;
        o1.y = (wgt * sm_[nt][3] + li[nt][3]) * id1;
        *(float2*)&out[xb + (size_t)r0 * 64 + c] = o0;
        *(float2*)&out[xb + (size_t)r1 * 64 + c] = o1;
    }
}

extern "C" void kernel_launch(void* const* d_in, const int* in_sizes, int n_in,
                              void* d_out, int out_size) {
    const float* Q = (const float*)d_in[0];
    const float* K = (const float*)d_in[1];
    const float* V = (const float*)d_in[2];
    const float* W = (const float*)d_in[3];
    const float* A = (const float*)d_in[4];
    float* out = (float*)d_out;

    cudaFuncSetAttribute(phase1_kernel, cudaFuncAttributeMaxDynamicSharedMemorySize, 47104);
    cudaFuncSetAttribute(phase2_kernel, cudaFuncAttributeMaxDynamicSharedMemorySize, 55296);

    prep_kernel<<<HH, 256>>>(W);
    phase1_kernel<<<BH * NB, 256, 47104>>>(K, V);
    scanS_kernel<<<dim3(5, BH), 256>>>();
    phase2_kernel<<<BH * NB, 256, 55296>>>(Q, K, V, A, out);
}